// round 6
// baseline (speedup 1.0000x reference)
#include <cuda_runtime.h>
#include <cuda_bf16.h>
#include <cstdint>

// DotAttentionEluX — math collapses:
//   attn[i,j] = ks_j / sum_j ks_j  (query cancels in row normalization)
//   out[b,h,i,:] = (sum_j ks_j * v_j) / (sum_j ks_j)   -- same for every row i
// with ks_j = sum_d (elu(k[b,h,j,d]) + 1).
//
// R4: STG.128 issue cost bound the write (7.3us). R5: one 32KB bulk copy per
// 512 CTAs was latency-bound (all pipes idle, occ 13%). R6: 2048 CTAs x 8KB
// bulk copies -> ~14 resident CTAs/SM, overlapped latency chains.

static constexpr int B_ = 4, H_ = 8, L_ = 2048, D_ = 64;
static constexpr int BH = B_ * H_;                  // 32
static constexpr int NSPLIT = 16;
static constexpr int ROWS_PER_SPLIT = L_ / NSPLIT;  // 128
static constexpr int WARPS = 8;

__device__ float g_num[BH * NSPLIT * D_];
__device__ float g_den[BH * NSPLIT];

__device__ __forceinline__ float elu1(float x) {
    return x > 0.0f ? x + 1.0f : __expf(x);
}

__global__ __launch_bounds__(256) void accum_kernel(
    const float* __restrict__ K, const float* __restrict__ V)
{
    const int blk   = blockIdx.x;       // 0..511
    const int bh    = blk / NSPLIT;
    const int split = blk % NSPLIT;
    const int warp  = threadIdx.x >> 5;
    const int lane  = threadIdx.x & 31;
    const int half  = lane >> 4;        // 0/1: which row of the pair
    const int q     = lane & 15;        // float4 slot within the row

    // Warp handles 8 row-pairs; lanes 0-15 -> even row, 16-31 -> odd row.
    // One LDG.128 per warp covers 2 full rows (512B, perfectly coalesced).
    const int row0 = split * ROWS_PER_SPLIT;
    const size_t base = ((size_t)bh * L_ + row0 + (size_t)warp * 2 + half) * D_
                        + (size_t)q * 4;
    const float4* __restrict__ Kp = reinterpret_cast<const float4*>(K + base);
    const float4* __restrict__ Vp = reinterpret_cast<const float4*>(V + base);
    constexpr int STRIDE4 = WARPS * 2 * D_ / 4;          // float4s between pairs
    constexpr int NPAIR   = ROWS_PER_SPLIT / (WARPS * 2); // 8

    float n0 = 0.f, n1 = 0.f, n2 = 0.f, n3 = 0.f, den = 0.f;

    #pragma unroll
    for (int r = 0; r < NPAIR; r++) {
        float4 kk = Kp[(size_t)r * STRIDE4];
        float4 vv = Vp[(size_t)r * STRIDE4];
        float ks = elu1(kk.x) + elu1(kk.y) + elu1(kk.z) + elu1(kk.w);
        // Reduce across the 16 lanes of this half-warp (xor stays in-group).
        #pragma unroll
        for (int o = 8; o; o >>= 1)
            ks += __shfl_xor_sync(0xffffffffu, ks, o);
        n0 += ks * vv.x;
        n1 += ks * vv.y;
        n2 += ks * vv.z;
        n3 += ks * vv.w;
        if (q == 0) den += ks;
    }

    __shared__ float4 s_num[WARPS * 2][D_ / 4];
    __shared__ float  s_den[WARPS * 2];
    const int wh = warp * 2 + half;
    s_num[wh][q] = make_float4(n0, n1, n2, n3);
    if (q == 0) s_den[wh] = den;
    __syncthreads();

    const int t = threadIdx.x;
    if (t < D_) {
        const float* sn = reinterpret_cast<const float*>(s_num);
        float s = 0.0f;
        #pragma unroll
        for (int w = 0; w < WARPS * 2; w++) s += sn[w * D_ + t];
        g_num[(bh * NSPLIT + split) * D_ + t] = s;
    }
    if (t == D_) {
        float s = 0.0f;
        #pragma unroll
        for (int w = 0; w < WARPS * 2; w++) s += s_den[w];
        g_den[bh * NSPLIT + split] = s;
    }
}

// ---- bcast: 64 chunks x 32 bh = 2048 CTAs, each bulk-stores 8 KB ----
static constexpr int NCHUNK = 64;
static constexpr int ROWS_PER_CHUNK = L_ / NCHUNK;          // 32 rows
static constexpr int CHUNK_BYTES = ROWS_PER_CHUNK * D_ * 4; // 8192

__global__ __launch_bounds__(128) void bcast_kernel(float* __restrict__ out)
{
    const int chunk = blockIdx.x;   // 0..63
    const int bh    = blockIdx.y;   // 0..31
    const int t     = threadIdx.x;  // 128 threads

    __shared__ alignas(128) float4 s_buf[ROWS_PER_CHUNK * (D_ / 4)]; // 8 KB
    __shared__ float4 s_w4[D_ / 4];

    // Finish the split reduction, w = num/den (64 threads).
    if (t < D_) {
        const float* __restrict__ pn = g_num + bh * NSPLIT * D_ + t;
        float num = 0.0f, den = 0.0f;
        #pragma unroll
        for (int sp = 0; sp < NSPLIT; sp++) {
            num += pn[sp * D_];
            den += g_den[bh * NSPLIT + sp];
        }
        reinterpret_cast<float*>(s_w4)[t] = num / den;
    }
    __syncthreads();

    // Replicate the 256B row into 32 rows: 4 conflict-free STS.128 per thread.
    {
        const float4 v = s_w4[t & 15];
        const int r0 = t >> 4;           // 0..7
        #pragma unroll
        for (int i = 0; i < ROWS_PER_CHUNK / 8; i++)     // 4 iters
            s_buf[(r0 + 8 * i) * (D_ / 4) + (t & 15)] = v;
    }
    __syncthreads();

    // One 8 KB bulk async store per CTA.
    if (t == 0) {
        asm volatile("fence.proxy.async.shared::cta;" ::: "memory");
        const float* gdst = out + ((size_t)bh * L_ + (size_t)chunk * ROWS_PER_CHUNK) * D_;
        uint32_t saddr = (uint32_t)__cvta_generic_to_shared(s_buf);
        asm volatile(
            "cp.async.bulk.global.shared::cta.bulk_group [%0], [%1], %2;"
            :: "l"(gdst), "r"(saddr), "r"((int)CHUNK_BYTES) : "memory");
        asm volatile("cp.async.bulk.commit_group;" ::: "memory");
        // CTA (and its SMEM) must stay alive until the copy has read SMEM.
        asm volatile("cp.async.bulk.wait_group.read 0;" ::: "memory");
    }
}

extern "C" void kernel_launch(void* const* d_in, const int* in_sizes, int n_in,
                              void* d_out, int out_size)
{
    // metadata order: query, key, value. Query is mathematically irrelevant.
    const float* K = (const float*)d_in[1];
    const float* V = (const float*)d_in[2];
    float* out = (float*)d_out;

    accum_kernel<<<BH * NSPLIT, 256>>>(K, V);
    bcast_kernel<<<dim3(NCHUNK, BH), 128>>>(out);
}